// round 2
// baseline (speedup 1.0000x reference)
#include <cuda_runtime.h>

// Fully fused kernel:
//   t4[i,n,l] = sum_{j,k} x[j, n, l+k-1] * w2[i,j,k]   (zero-padded 3-tap conv)
//   out[i,(n+1)%56,l] += w1[i,0] * t4[i,n,l]
//   out[i,(n+2)%56,l] += w1[i,1] * t4[i,n,l]
// Each output element receives exactly 2 atomic adds onto a memset-0 base;
// 2-operand float add is commutative bitwise -> deterministic result.
//
// Grid (ihalf=2, n=56), 256 threads. Threads split the j-reduction in half
// (jh = tid>>7); halves are combined through a padded smem buffer so each
// output location still sees exactly 2 global adds.
__global__ __launch_bounds__(256) void fused_conv_mix_kernel(
    const float* __restrict__ x,
    const float* __restrict__ w1,
    const float* __restrict__ w2,
    float* __restrict__ out) {

    __shared__ float xs[64 * 58];      // one spatial row, zero-padded halo
    __shared__ float w2s[192 * 33];    // transposed weights [jk][i_local], +1 pad
    __shared__ float rbuf[128 * 15];   // j-split partials, stride 15 (coprime 32)

    const int n     = blockIdx.y;
    const int ihalf = blockIdx.x;
    const int ibase = ihalf * 32;
    const int tid   = threadIdx.x;

    // Load x row n, all 64 channels, with zero halo at padded cols 0 / 57.
    for (int idx = tid; idx < 64 * 58; idx += 256) {
        int j = idx / 58;
        int c = idx % 58;
        float v = 0.0f;
        if (c >= 1 && c <= 56) v = x[(j * 56 + n) * 56 + (c - 1)];
        xs[idx] = v;
    }
    // Load this half's 32 output-channels of w2, transposed to [jk][i_local].
    for (int idx = tid; idx < 32 * 192; idx += 256) {
        int il = idx / 192;
        int jk = idx % 192;
        w2s[jk * 33 + il] = w2[(ibase + il) * 192 + jk];
    }
    __syncthreads();

    const int jh = tid >> 7;      // 0/1 : which half of the j-reduction
    const int t  = tid & 127;
    const int ip = t >> 3;        // 0..15 : channel pair
    const int lg = t & 7;         // 0..7  : column group
    const int l0 = lg * 7;        // output columns l0..l0+6
    const int j0 = jh * 32;

    float acc[2][7];
#pragma unroll
    for (int c = 0; c < 2; ++c)
#pragma unroll
        for (int q = 0; q < 7; ++q) acc[c][q] = 0.0f;

#pragma unroll 4
    for (int jj = 0; jj < 32; ++jj) {
        const int j = j0 + jj;
        float xv[9];
#pragma unroll
        for (int q = 0; q < 9; ++q) xv[q] = xs[j * 58 + l0 + q];

#pragma unroll
        for (int c = 0; c < 2; ++c) {
            const int il = ip * 2 + c;
            const float wk0 = w2s[(j * 3 + 0) * 33 + il];
            const float wk1 = w2s[(j * 3 + 1) * 33 + il];
            const float wk2 = w2s[(j * 3 + 2) * 33 + il];
#pragma unroll
            for (int q = 0; q < 7; ++q) {
                acc[c][q] = fmaf(xv[q],     wk0,
                           fmaf(xv[q + 1], wk1,
                           fmaf(xv[q + 2], wk2, acc[c][q])));
            }
        }
    }

    // Combine the two j-halves deterministically through smem.
    if (jh == 1) {
#pragma unroll
        for (int c = 0; c < 2; ++c)
#pragma unroll
            for (int q = 0; q < 7; ++q)
                rbuf[t * 15 + c * 7 + q] = acc[c][q];
    }
    __syncthreads();

    if (jh == 0) {
        const int r1 = (n + 1) % 56;   // receives w1[i,0] * t4[i,n,:]
        const int r2 = (n + 2) % 56;   // receives w1[i,1] * t4[i,n,:]
#pragma unroll
        for (int c = 0; c < 2; ++c) {
            const int i = ibase + ip * 2 + c;
            const float w10 = w1[2 * i];
            const float w11 = w1[2 * i + 1];
#pragma unroll
            for (int q = 0; q < 7; ++q) {
                const float f = acc[c][q] + rbuf[t * 15 + c * 7 + q];
                const int l = l0 + q;
                atomicAdd(&out[(i * 56 + r1) * 56 + l], w10 * f);  // -> REDG
                atomicAdd(&out[(i * 56 + r2) * 56 + l], w11 * f);  // -> REDG
            }
        }
    }
}

extern "C" void kernel_launch(void* const* d_in, const int* in_sizes, int n_in,
                              void* d_out, int out_size) {
    const float* x  = (const float*)d_in[0];   // (1,64,56,56)
    const float* w1 = (const float*)d_in[1];   // (64,2)
    const float* w2 = (const float*)d_in[2];   // (64,64,3)
    float* out = (float*)d_out;                // (1,64,56,56)

    // Output must start at zero: each element accumulates exactly 2 REDs.
    cudaMemsetAsync(out, 0, (size_t)out_size * sizeof(float), 0);

    dim3 grid(2, 56);
    fused_conv_mix_kernel<<<grid, 256>>>(x, w1, w2, out);
}

// round 3
// speedup vs baseline: 1.1744x; 1.1744x over previous
#include <cuda_runtime.h>

// ---------------------------------------------------------------------------
// Math (derived in R1, verified numerically):
//   t4[i,n,l]  = sum_{j,k} x[j, n, l+k-1] * w2[i,j,k]   (zero-padded 3-tap)
//   out[i,m,l] = w1[i,0]*t4[i,(m-1)%56,l] + w1[i,1]*t4[i,(m-2)%56,l]
//
// One block per (channel-half, output row m). The block computes BOTH needed
// t4 rows (na=m-1, nb=m-2) over the full j=64 reduction and writes out with
// plain stores: no atomics, no memset, single graph node.
//
// 512 threads = 4-way j-split (jq) x 16 channel-pairs (ip) x 8 col-groups (lg).
// Accumulators are f32x2-packed over the channel pair -> fma.rn.f32x2 halves
// FMA instruction count (FFMA-3reg is half-rate on sm_103a).
// ---------------------------------------------------------------------------

using ull = unsigned long long;

__device__ __forceinline__ ull pack2b(float v) {
    ull r; asm("mov.b64 %0, {%1, %1};" : "=l"(r) : "f"(v)); return r;
}
__device__ __forceinline__ ull pack2(float lo, float hi) {
    ull r; asm("mov.b64 %0, {%1, %2};" : "=l"(r) : "f"(lo), "f"(hi)); return r;
}
__device__ __forceinline__ ull fma2(ull a, ull b, ull c) {
    ull d; asm("fma.rn.f32x2 %0, %1, %2, %3;" : "=l"(d) : "l"(a), "l"(b), "l"(c)); return d;
}
__device__ __forceinline__ ull add2(ull a, ull b) {
    ull d; asm("add.rn.f32x2 %0, %1, %2;" : "=l"(d) : "l"(a), "l"(b)); return d;
}
__device__ __forceinline__ void unpack2(ull p, float& lo, float& hi) {
    asm("mov.b64 {%0, %1}, %2;" : "=f"(lo), "=f"(hi) : "l"(p));
}

// Shared-memory arena (dynamic):
//   xsa: 64*58 floats  (row na, zero halo)        [0      .. 3712)
//   xsb: 64*58 floats  (row nb, zero halo)        [3712   .. 7424)
//   w2p: 16*193 ull    (packed channel-pair wts)  [7424   .. 7424+6176)
//   rbuf overlays arena base after main loop: 384*14 ull = 5376 ull
static constexpr int XSA_OFF  = 0;
static constexpr int XSB_OFF  = 64 * 58;
static constexpr int W2P_OFFF = 2 * 64 * 58;          // in floats
static constexpr int ARENA_FLOATS = W2P_OFFF + 16 * 193 * 2;
static constexpr int ARENA_BYTES  = ARENA_FLOATS * 4; // 54400

__global__ __launch_bounds__(512, 1) void fused_kernel(
    const float* __restrict__ x,
    const float* __restrict__ w1,
    const float* __restrict__ w2,
    float* __restrict__ out) {

    extern __shared__ float arena[];
    float* xsa = arena + XSA_OFF;
    float* xsb = arena + XSB_OFF;
    ull*   w2p = reinterpret_cast<ull*>(arena + W2P_OFFF);

    const int m     = blockIdx.y;
    const int ihalf = blockIdx.x;
    const int ibase = ihalf * 32;
    const int na    = (m + 55) % 56;   // m-1 mod 56
    const int nb    = (m + 54) % 56;   // m-2 mod 56
    const int tid   = threadIdx.x;

    // Zero halos (padded cols 0 and 57 of both row buffers).
    if (tid < 256) {
        int j = tid >> 2;
        int w = tid & 3;
        float* buf = (w & 2) ? xsb : xsa;
        buf[j * 58 + ((w & 1) ? 57 : 0)] = 0.0f;
    }

    // Load both x rows (vectorized float4: 2 x 64ch x 14 float4 = 1792).
    for (int idx = tid; idx < 1792; idx += 512) {
        int rb = idx >= 896;
        int q  = rb ? idx - 896 : idx;
        int j  = q / 14;
        int c4 = q % 14;
        const int n = rb ? nb : na;
        float4 v = *reinterpret_cast<const float4*>(&x[(j * 56 + n) * 56 + c4 * 4]);
        float* buf = rb ? xsb : xsa;
        float* d = &buf[j * 58 + 1 + c4 * 4];
        d[0] = v.x; d[1] = v.y; d[2] = v.z; d[3] = v.w;
    }

    // Load + pack this half's weights: w2p[ip*193 + jk] = {w2[i0][jk], w2[i1][jk]}.
    // Consecutive tid -> consecutive jk: coalesced gmem, conflict-free STS.64.
    for (int idx = tid; idx < 16 * 192; idx += 512) {
        int ip = idx / 192;
        int jk = idx % 192;
        int i0 = ibase + 2 * ip;
        w2p[ip * 193 + jk] = pack2(w2[i0 * 192 + jk], w2[(i0 + 1) * 192 + jk]);
    }
    __syncthreads();

    const int jq = tid >> 7;        // 0..3 : j-quarter
    const int t  = tid & 127;
    const int ip = t >> 3;          // 0..15 : channel pair
    const int lg = t & 7;           // 0..7  : column group
    const int l0 = lg * 7;
    const int j0 = jq * 16;

    ull acc_a[7], acc_b[7];
#pragma unroll
    for (int q = 0; q < 7; ++q) { acc_a[q] = 0ull; acc_b[q] = 0ull; }

#pragma unroll 4
    for (int jj = 0; jj < 16; ++jj) {
        const int j = j0 + jj;
        const float* xa = &xsa[j * 58 + l0];
        const float* xb = &xsb[j * 58 + l0];
        const ull wk0 = w2p[ip * 193 + 3 * j + 0];
        const ull wk1 = w2p[ip * 193 + 3 * j + 1];
        const ull wk2 = w2p[ip * 193 + 3 * j + 2];

        ull pa[9], pb[9];
#pragma unroll
        for (int q = 0; q < 9; ++q) { pa[q] = pack2b(xa[q]); pb[q] = pack2b(xb[q]); }

#pragma unroll
        for (int q = 0; q < 7; ++q) {
            acc_a[q] = fma2(pa[q], wk0, fma2(pa[q + 1], wk1, fma2(pa[q + 2], wk2, acc_a[q])));
            acc_b[q] = fma2(pb[q], wk0, fma2(pb[q + 1], wk1, fma2(pb[q + 2], wk2, acc_b[q])));
        }
    }

    // Combine the 4 j-quarters through smem (overlaying the arena).
    __syncthreads();   // all xs/w2p reads complete before overlay
    ull* rbuf = reinterpret_cast<ull*>(arena);
    if (jq != 0) {
        ull* dst = &rbuf[((jq - 1) * 128 + t) * 14];
#pragma unroll
        for (int q = 0; q < 7; ++q) { dst[q] = acc_a[q]; dst[7 + q] = acc_b[q]; }
    }
    __syncthreads();

    if (jq == 0) {
#pragma unroll
        for (int p = 0; p < 3; ++p) {
            const ull* src = &rbuf[(p * 128 + t) * 14];
#pragma unroll
            for (int q = 0; q < 7; ++q) {
                acc_a[q] = add2(acc_a[q], src[q]);
                acc_b[q] = add2(acc_b[q], src[7 + q]);
            }
        }
        const int i0 = ibase + 2 * ip;
        const int i1 = i0 + 1;
        const float w10_0 = w1[2 * i0],     w11_0 = w1[2 * i0 + 1];
        const float w10_1 = w1[2 * i1],     w11_1 = w1[2 * i1 + 1];
#pragma unroll
        for (int q = 0; q < 7; ++q) {
            float a0, a1, b0, b1;
            unpack2(acc_a[q], a0, a1);
            unpack2(acc_b[q], b0, b1);
            out[(i0 * 56 + m) * 56 + l0 + q] = fmaf(w10_0, a0, w11_0 * b0);
            out[(i1 * 56 + m) * 56 + l0 + q] = fmaf(w10_1, a1, w11_1 * b1);
        }
    }
}

extern "C" void kernel_launch(void* const* d_in, const int* in_sizes, int n_in,
                              void* d_out, int out_size) {
    const float* x  = (const float*)d_in[0];   // (1,64,56,56)
    const float* w1 = (const float*)d_in[1];   // (64,2)
    const float* w2 = (const float*)d_in[2];   // (64,64,3)
    float* out = (float*)d_out;                // (1,64,56,56)

    static bool attr_set = false;
    if (!attr_set) {
        cudaFuncSetAttribute(fused_kernel,
                             cudaFuncAttributeMaxDynamicSharedMemorySize,
                             ARENA_BYTES);
        attr_set = true;
    }

    dim3 grid(2, 56);
    fused_kernel<<<grid, 512, ARENA_BYTES>>>(x, w1, w2, out);
}